// round 8
// baseline (speedup 1.0000x reference)
#include <cuda_runtime.h>
#include <math.h>

#define D_ 96
#define H_ 192
#define W_ 192
#define B_ 2
#define VOL (D_*H_*W_)            // 3538944
#define RAD 12
#define KLEN 25
#define SLAB 8
#define NSLAB (D_/SLAB)           // 12
#define PW (W_ + 2)               // 194 (sobel halo)
#define WB (W_ + 2*RAD)           // 216
#define HP (H_ + 2*RAD)           // 216
#define DP (D_ + 2*RAD)           // 120
#define NPART ((W_/32) * H_)      // 1152 partials per batch
#define K3_BLOCKS ((W_/32) * H_ * B_)   // 2304

typedef unsigned long long u64;

// ---- static scratch ----
__device__ u64      d_mg[B_*VOL];    // packed {mag, g} as f32x2
__device__ float    d_pnum[B_*NPART];
__device__ float    d_pden[B_*NPART];
__device__ unsigned d_count = 0;

// ---------------------------------------------------------------------------
__device__ __forceinline__ u64 pack2(float a, float b) {
    u64 r; asm("mov.b64 %0, {%1,%2};" : "=l"(r) : "f"(a), "f"(b)); return r;
}
__device__ __forceinline__ void fma2(u64& d, u64 a, u64 b) {
    asm("fma.rn.f32x2 %0, %1, %2, %3;" : "=l"(d) : "l"(a), "l"(b), "l"(d));
}
__device__ __forceinline__ float2 unpack2(u64 v) {
    float x, y; asm("mov.b64 {%0,%1}, %2;" : "=f"(x), "=f"(y) : "l"(v));
    return make_float2(x, y);
}

// MONAI gaussian_1d tap (sigma=3, erf mode), t in [0,13): x = t-12
__device__ __forceinline__ float tapval(int t) {
    float x = (float)(t - RAD);
    const float c = 0.70710678f / 3.0f;
    return fmaxf(0.5f * (erff(c*(x+0.5f)) - erff(c*(x-0.5f))), 0.0f);
}
// compute 13 packed taps into smem (call from all threads; sync outside)
__device__ __forceinline__ void make_taps(u64* sk, int tid) {
    if (tid < 13) { float k = tapval(tid); sk[tid] = pack2(k, k); }
}
#define TAP2(t) kp[(t) < 13 ? (t) : 24 - (t)]

// ---------------------------------------------------------------------------
// K1: rint-sum -> 3D Sobel magnitude + guidance binarize -> W-blur (packed).
// 4-slot plane ring: ONE __syncthreads per d-iteration.
__global__ __launch_bounds__(256) void sobel_blurW_kernel(const float* __restrict__ outs,
                                                          const float* __restrict__ guid) {
    __shared__ float pl[4][10][PW];    // 31.0 KB
    __shared__ u64   wg[8][WB];        // 13.8 KB (warp-private rows)
    __shared__ u64   sk[13];
    const int tx = threadIdx.x, ty = threadIdx.y;
    const int tid = ty * 32 + tx;
    const int h0 = blockIdx.x * 8;
    const int d0 = blockIdx.y * SLAB;
    const int b  = blockIdx.z;
    const float* o0 = outs + (size_t)(b*2+0)*VOL;
    const float* o1 = outs + (size_t)(b*2+1)*VOL;
    const float* g0 = guid + (size_t)(b*2+0)*VOL;
    const float* g1 = guid + (size_t)(b*2+1)*VOL;

    make_taps(sk, tid);
    if (tx < RAD) { wg[ty][tx] = 0ULL; wg[ty][W_ + RAD + tx] = 0ULL; }

    auto loadPlane = [&](int d) {
        int slot = d & 3;
        for (int i = tid; i < 10 * PW; i += 256) {
            int lh = i / PW, lw = i - lh * PW;
            int gh = h0 + lh - 1, gw = lw - 1;
            float s = 0.0f;
            if ((unsigned)d < (unsigned)D_ && (unsigned)gh < (unsigned)H_ &&
                (unsigned)gw < (unsigned)W_) {
                int idx = (d * H_ + gh) * W_ + gw;
                s = rintf(__ldg(o0 + idx)) + rintf(__ldg(o1 + idx));
            }
            pl[slot][lh][lw] = s;
        }
    };

    loadPlane(d0 - 1 + 4);   // slot (d0-1)&3 via +4 to keep d&3 well-defined
    // note: (d0-1+4)&3 == (d0-1)&3 and bounds check uses real d below
    // redo with real coordinate for correctness of the predicate:
    {
        int d = d0 - 1, slot = (d0 + 3) & 3;
        for (int i = tid; i < 10 * PW; i += 256) {
            int lh = i / PW, lw = i - lh * PW;
            int gh = h0 + lh - 1, gw = lw - 1;
            float s = 0.0f;
            if ((unsigned)d < (unsigned)D_ && (unsigned)gh < (unsigned)H_ &&
                (unsigned)gw < (unsigned)W_) {
                int idx = (d * H_ + gh) * W_ + gw;
                s = rintf(__ldg(o0 + idx)) + rintf(__ldg(o1 + idx));
            }
            pl[slot][lh][lw] = s;
        }
    }
    loadPlane(d0);
    __syncthreads();

    u64 kp[13];
#pragma unroll
    for (int t = 0; t < 13; t++) kp[t] = sk[t];

    const int h = h0 + ty, lh = ty + 1;
    for (int d = d0; d < d0 + SLAB; d++) {
        loadPlane(d + 1);
        __syncthreads();                 // the only barrier per iteration
        const float (*P)[PW] = pl[(d + 3) & 3];
        const float (*C)[PW] = pl[d & 3];
        const float (*N)[PW] = pl[(d + 1) & 3];
#pragma unroll
        for (int c = 0; c < 6; c++) {
            int w = c * 32 + tx, lw = w + 1;
            float c_mm = C[lh-1][lw-1], c_m0 = C[lh-1][lw], c_mp = C[lh-1][lw+1];
            float c_0m = C[lh  ][lw-1],                     c_0p = C[lh  ][lw+1];
            float c_pm = C[lh+1][lw-1], c_p0 = C[lh+1][lw], c_pp = C[lh+1][lw+1];
            float xv = (c_pm + 2.0f*c_p0 + c_pp) - (c_mm + 2.0f*c_m0 + c_mp);
            float xh = (c_mp + 2.0f*c_0p + c_pp) - (c_mm + 2.0f*c_0m + c_pm);
            float xd = (P[lh+1][lw] - P[lh-1][lw]) + 2.0f*(c_p0 - c_m0)
                     + (N[lh+1][lw] - N[lh-1][lw]);
            float mag = sqrtf(xv*xv + xh*xh + xd*xd + 1e-6f);
            int gidx = (d * H_ + h) * W_ + w;
            float gv = (__ldg(g0 + gidx) != 0.0f ? 1.0f : 0.0f)
                     + (__ldg(g1 + gidx) != 0.0f ? 1.0f : 0.0f);
            wg[ty][RAD + w] = pack2(mag, gv);
        }
        __syncwarp();
        const int wb = tx * 6;
        u64 acc[6] = {0,0,0,0,0,0};
#pragma unroll
        for (int j = 0; j < 6 + 2*RAD; j++) {
            u64 x = wg[ty][wb + j];
#pragma unroll
            for (int i = 0; i < 6; i++) {
                int t = j - i;
                if (t >= 0 && t < KLEN) fma2(acc[i], TAP2(t), x);
            }
        }
        size_t base = (((size_t)b*D_ + d)*H_ + h)*W_ + wb;
#pragma unroll
        for (int i = 0; i < 6; i++) d_mg[base + i] = acc[i];
        __syncwarp();   // wg reuse next iter is warp-local
    }
}

// ---------------------------------------------------------------------------
// K2: H-blur both fields (packed), in place. Block (16,16), 16 w-cols, full H.
__global__ __launch_bounds__(256) void blurH_kernel() {
    __shared__ u64 sh[HP][16];         // 27648 B
    __shared__ u64 sk[13];
    const int tx = threadIdx.x, ty = threadIdx.y;
    const int tid = ty * 16 + tx;
    const int w0 = blockIdx.x * 16, d = blockIdx.y, b = blockIdx.z;
    size_t base = ((size_t)b*D_ + d) * (size_t)(H_*W_);

    make_taps(sk, tid);
    for (int hl = ty; hl < HP; hl += 16) {
        int gh = hl - RAD;
        bool ok = (unsigned)gh < (unsigned)H_;
        size_t idx = base + (size_t)(ok ? gh : 0)*W_ + w0 + tx;
        sh[hl][tx] = ok ? d_mg[idx] : 0ULL;
    }
    __syncthreads();

    u64 kp[13];
#pragma unroll
    for (int t = 0; t < 13; t++) kp[t] = sk[t];

    const int hb = ty * 12;
    u64 acc[12] = {0,0,0,0,0,0,0,0,0,0,0,0};
#pragma unroll
    for (int j = 0; j < 12 + 2*RAD; j++) {
        u64 x = sh[hb + j][tx];
#pragma unroll
        for (int i = 0; i < 12; i++) {
            int t = j - i;
            if (t >= 0 && t < KLEN) fma2(acc[i], TAP2(t), x);
        }
    }
#pragma unroll
    for (int i = 0; i < 12; i++)
        d_mg[base + (size_t)(hb+i)*W_ + w0 + tx] = acc[i];
}

// ---------------------------------------------------------------------------
// K3: D-blur both fields (packed) + dot/sum reduction + last-block finalize.
__global__ __launch_bounds__(256) void blurD_reduce_kernel(float* __restrict__ out) {
    __shared__ u64 sh[DP][32];         // 30720 B
    __shared__ u64 sk[13];
    __shared__ float rn[256], rd[256];
    __shared__ bool isLast;
    const int tx = threadIdx.x, ty = threadIdx.y;
    const int tid = ty * 32 + tx;
    const int w0 = blockIdx.x * 32, h = blockIdx.y, b = blockIdx.z;
    size_t base = (size_t)b*VOL + (size_t)h*W_ + w0 + tx;

    make_taps(sk, tid);
    for (int dl = ty; dl < DP; dl += 8) {
        int gd = dl - RAD;
        bool ok = (unsigned)gd < (unsigned)D_;
        size_t idx = base + (size_t)(ok ? gd : 0) * (H_*W_);
        sh[dl][tx] = ok ? d_mg[idx] : 0ULL;
    }
    __syncthreads();

    u64 kp[13];
#pragma unroll
    for (int t = 0; t < 13; t++) kp[t] = sk[t];

    const int db = ty * 12;
    u64 acc[12] = {0,0,0,0,0,0,0,0,0,0,0,0};
#pragma unroll
    for (int j = 0; j < 12 + 2*RAD; j++) {
        u64 x = sh[db + j][tx];
#pragma unroll
        for (int i = 0; i < 12; i++) {
            int t = j - i;
            if (t >= 0 && t < KLEN) fma2(acc[i], TAP2(t), x);
        }
    }
    float num = 0.0f, den = 0.0f;
#pragma unroll
    for (int i = 0; i < 12; i++) {
        float2 v = unpack2(acc[i]);
        num += v.x * v.y;
        den += v.y;
    }

    rn[tid] = num; rd[tid] = den;
    __syncthreads();
    for (int s = 128; s > 0; s >>= 1) {
        if (tid < s) { rn[tid] += rn[tid + s]; rd[tid] += rd[tid + s]; }
        __syncthreads();
    }
    if (tid == 0) {
        int pb = blockIdx.y * gridDim.x + blockIdx.x;
        d_pnum[b*NPART + pb] = rn[0];
        d_pden[b*NPART + pb] = rd[0];
        __threadfence();
        unsigned prev = atomicAdd(&d_count, 1u);
        isLast = (prev == (unsigned)(K3_BLOCKS - 1));
    }
    __syncthreads();

    if (isLast) {
        __threadfence();   // all partials visible (all blocks arrived)
        for (int bb = 0; bb < B_; bb++) {
            float n = 0.0f, dsum = 0.0f;
            for (int i = tid; i < NPART; i += 256) {
                n    += d_pnum[bb*NPART + i];
                dsum += d_pden[bb*NPART + i];
            }
            rn[tid] = n; rd[tid] = dsum;
            __syncthreads();
            for (int s = 128; s > 0; s >>= 1) {
                if (tid < s) { rn[tid] += rn[tid + s]; rd[tid] += rd[tid + s]; }
                __syncthreads();
            }
            if (tid == 0) out[bb] = expf(-(rn[0] / (rd[0] + 1.0f)));
            __syncthreads();
        }
        if (tid == 0) d_count = 0;   // reset for next graph replay
    }
}

// ---------------------------------------------------------------------------
extern "C" void kernel_launch(void* const* d_in, const int* in_sizes, int n_in,
                              void* d_out, int out_size) {
    (void)in_sizes; (void)n_in; (void)out_size;
    const float* outs = (const float*)d_in[0];
    const float* guid = (const float*)d_in[1];
    float* out = (float*)d_out;

    {   // K1: sobel + W-blur (both fields, packed) -> d_mg
        dim3 grid(H_/8, NSLAB, B_);
        dim3 blk(32, 8);
        sobel_blurW_kernel<<<grid, blk>>>(outs, guid);
    }
    {   // K2: H-blur in place
        dim3 grid(W_/16, D_, B_);
        dim3 blk(16, 16);
        blurH_kernel<<<grid, blk>>>();
    }
    {   // K3: D-blur + reduction + finalize (last block)
        dim3 grid(W_/32, H_, B_);
        dim3 blk(32, 8);
        blurD_reduce_kernel<<<grid, blk>>>(out);
    }
}

// round 9
// speedup vs baseline: 1.1597x; 1.1597x over previous
#include <cuda_runtime.h>
#include <math.h>

#define D_ 96
#define H_ 192
#define W_ 192
#define B_ 2
#define VOL (D_*H_*W_)            // 3538944
#define RAD 12
#define KLEN 25
#define SLAB 8
#define NSLAB (D_/SLAB)           // 12
#define PW (W_ + 2)               // 194
#define WB (W_ + 2*RAD)           // 216
#define HP (H_ + 2*RAD)           // 216
#define DP (D_ + 2*RAD)           // 120
#define HT 4                      // h-tile in K1
#define PROWS (HT + 2)            // 6 rows per plane tile
#define PELEMS (PROWS * PW)       // 1164
#define NPART ((W_/32) * H_)      // 1152 partials per batch
#define K3_BLOCKS ((W_/32) * H_ * B_)   // 2304

typedef unsigned long long u64;

// ---- static scratch ----
__device__ u64      d_mg[B_*VOL];    // packed {mag, g} f32x2
__device__ float    d_pnum[B_*NPART];
__device__ float    d_pden[B_*NPART];
__device__ unsigned d_count = 0;

// ---------------------------------------------------------------------------
__device__ __forceinline__ u64 pack2(float a, float b) {
    u64 r; asm("mov.b64 %0, {%1,%2};" : "=l"(r) : "f"(a), "f"(b)); return r;
}
__device__ __forceinline__ void fma2(u64& d, u64 a, u64 b) {
    asm("fma.rn.f32x2 %0, %1, %2, %3;" : "=l"(d) : "l"(a), "l"(b), "l"(d));
}
__device__ __forceinline__ float2 unpack2(u64 v) {
    float x, y; asm("mov.b64 {%0,%1}, %2;" : "=f"(x), "=f"(y) : "l"(v));
    return make_float2(x, y);
}

// MONAI gaussian_1d tap (sigma=3, erf), t in [0,13)
__device__ __forceinline__ float tapval(int t) {
    float x = (float)(t - RAD);
    const float c = 0.70710678f / 3.0f;
    return fmaxf(0.5f * (erff(c*(x+0.5f)) - erff(c*(x-0.5f))), 0.0f);
}
__device__ __forceinline__ void make_taps(u64* sk, int tid) {
    if (tid < 13) { float k = tapval(tid); sk[tid] = pack2(k, k); }
}
#define TAP2(t) kp[(t) < 13 ? (t) : 24 - (t)]

// ---------------------------------------------------------------------------
// K1: rint-sum -> 3D Sobel mag + guidance binarize -> W-blur (packed f32x2).
// Software pipeline: S-plane(d+2) + guidance(d+1) prefetched into registers
// while computing plane d. One __syncthreads per iteration (4-slot ring).
// Block (32,4) = 128 threads; h-tile 4; full W.
__global__ __launch_bounds__(128) void sobel_blurW_kernel(const float* __restrict__ outs,
                                                          const float* __restrict__ guid) {
    __shared__ float pl[4][PROWS][PW];   // 18.6 KB
    __shared__ u64   wg[HT][WB];         // 6.9 KB (warp-private rows)
    __shared__ u64   sk[13];
    const int tx = threadIdx.x, ty = threadIdx.y;
    const int tid = ty * 32 + tx;
    const int h0 = blockIdx.x * HT;
    const int d0 = blockIdx.y * SLAB;
    const int b  = blockIdx.z;
    const float* o0 = outs + (size_t)(b*2+0)*VOL;
    const float* o1 = outs + (size_t)(b*2+1)*VOL;
    const float* g0 = guid + (size_t)(b*2+0)*VOL;
    const float* g1 = guid + (size_t)(b*2+1)*VOL;
    const int h = h0 + ty;

    make_taps(sk, tid);
    if (tx < RAD) { wg[ty][tx] = 0ULL; wg[ty][W_ + RAD + tx] = 0ULL; }

    // direct load (prologue only): plane d -> smem slot d&3
    auto loadPlaneDirect = [&](int d) {
        int slot = d & 3;
        for (int i = tid; i < PELEMS; i += 128) {
            int lh = i / PW, lw = i - lh * PW;
            int gh = h0 + lh - 1, gw = lw - 1;
            float s = 0.0f;
            if ((unsigned)d < (unsigned)D_ && (unsigned)gh < (unsigned)H_ &&
                (unsigned)gw < (unsigned)W_) {
                int idx = (d * H_ + gh) * W_ + gw;
                s = rintf(__ldg(o0 + idx)) + rintf(__ldg(o1 + idx));
            }
            pl[slot][lh][lw] = s;
        }
    };
    // prefetch plane d into registers
    auto prefetchS = [&](int d, float* sreg) {
#pragma unroll
        for (int k = 0; k < 10; k++) {
            int i = tid + k * 128;
            float s = 0.0f;
            if (i < PELEMS) {
                int lh = i / PW, lw = i - lh * PW;
                int gh = h0 + lh - 1, gw = lw - 1;
                if ((unsigned)d < (unsigned)D_ && (unsigned)gh < (unsigned)H_ &&
                    (unsigned)gw < (unsigned)W_) {
                    int idx = (d * H_ + gh) * W_ + gw;
                    s = rintf(__ldg(o0 + idx)) + rintf(__ldg(o1 + idx));
                }
            }
            sreg[k] = s;
        }
    };
    auto storeS = [&](int d, const float* sreg) {
        int slot = d & 3;
#pragma unroll
        for (int k = 0; k < 10; k++) {
            int i = tid + k * 128;
            if (i < PELEMS) {
                int lh = i / PW, lw = i - lh * PW;
                pl[slot][lh][lw] = sreg[k];
            }
        }
    };
    // prefetch guidance row for plane d (raw values; combined at use)
    auto prefetchG = [&](int d, float* ga, float* gb_) {
        bool okd = (unsigned)d < (unsigned)D_;
#pragma unroll
        for (int c = 0; c < 6; c++) {
            int w = c * 32 + tx;
            int gidx = (d * H_ + h) * W_ + w;
            ga[c]  = okd ? __ldg(g0 + gidx) : 0.0f;
            gb_[c] = okd ? __ldg(g1 + gidx) : 0.0f;
        }
    };

    float sreg[10], ga[6], gb2[6];
    loadPlaneDirect(d0 - 1);
    loadPlaneDirect(d0);
    prefetchS(d0 + 1, sreg);
    prefetchG(d0, ga, gb2);
    __syncthreads();

    u64 kp[13];
#pragma unroll
    for (int t = 0; t < 13; t++) kp[t] = sk[t];

    const int lh = ty + 1;
    for (int d = d0; d < d0 + SLAB; d++) {
        storeS(d + 1, sreg);                      // consume S prefetch
        float gv[6];
#pragma unroll
        for (int c = 0; c < 6; c++)
            gv[c] = (ga[c] != 0.0f ? 1.0f : 0.0f) + (gb2[c] != 0.0f ? 1.0f : 0.0f);
        prefetchS(d + 2, sreg);                   // overlap with compute below
        prefetchG(d + 1, ga, gb2);
        __syncthreads();                          // only barrier per iter

        const float (*P)[PW] = pl[(d + 3) & 3];
        const float (*C)[PW] = pl[d & 3];
        const float (*N)[PW] = pl[(d + 1) & 3];
#pragma unroll
        for (int c = 0; c < 6; c++) {
            int w = c * 32 + tx, lw = w + 1;
            float c_mm = C[lh-1][lw-1], c_m0 = C[lh-1][lw], c_mp = C[lh-1][lw+1];
            float c_0m = C[lh  ][lw-1],                     c_0p = C[lh  ][lw+1];
            float c_pm = C[lh+1][lw-1], c_p0 = C[lh+1][lw], c_pp = C[lh+1][lw+1];
            float xv = (c_pm + 2.0f*c_p0 + c_pp) - (c_mm + 2.0f*c_m0 + c_mp);
            float xh = (c_mp + 2.0f*c_0p + c_pp) - (c_mm + 2.0f*c_0m + c_pm);
            float xd = (P[lh+1][lw] - P[lh-1][lw]) + 2.0f*(c_p0 - c_m0)
                     + (N[lh+1][lw] - N[lh-1][lw]);
            float mag = sqrtf(xv*xv + xh*xh + xd*xd + 1e-6f);
            wg[ty][RAD + w] = pack2(mag, gv[c]);
        }
        __syncwarp();
        const int wb = tx * 6;
        u64 acc[6] = {0,0,0,0,0,0};
#pragma unroll
        for (int j = 0; j < 6 + 2*RAD; j++) {
            u64 x = wg[ty][wb + j];
#pragma unroll
            for (int i = 0; i < 6; i++) {
                int t = j - i;
                if (t >= 0 && t < KLEN) fma2(acc[i], TAP2(t), x);
            }
        }
        size_t base = (((size_t)b*D_ + d)*H_ + h)*W_ + wb;
#pragma unroll
        for (int i = 0; i < 6; i++) d_mg[base + i] = acc[i];
        __syncwarp();   // wg rows are warp-private; pl slot written next iter is disjoint
    }
}

// ---------------------------------------------------------------------------
// K2: H-blur both fields (packed), in place. Block (16,16), 16 w-cols, full H.
__global__ __launch_bounds__(256) void blurH_kernel() {
    __shared__ u64 sh[HP][16];         // 27648 B
    __shared__ u64 sk[13];
    const int tx = threadIdx.x, ty = threadIdx.y;
    const int tid = ty * 16 + tx;
    const int w0 = blockIdx.x * 16, d = blockIdx.y, b = blockIdx.z;
    size_t base = ((size_t)b*D_ + d) * (size_t)(H_*W_);

    make_taps(sk, tid);
    for (int hl = ty; hl < HP; hl += 16) {
        int gh = hl - RAD;
        bool ok = (unsigned)gh < (unsigned)H_;
        size_t idx = base + (size_t)(ok ? gh : 0)*W_ + w0 + tx;
        sh[hl][tx] = ok ? d_mg[idx] : 0ULL;
    }
    __syncthreads();

    u64 kp[13];
#pragma unroll
    for (int t = 0; t < 13; t++) kp[t] = sk[t];

    const int hb = ty * 12;
    u64 acc[12] = {0,0,0,0,0,0,0,0,0,0,0,0};
#pragma unroll
    for (int j = 0; j < 12 + 2*RAD; j++) {
        u64 x = sh[hb + j][tx];
#pragma unroll
        for (int i = 0; i < 12; i++) {
            int t = j - i;
            if (t >= 0 && t < KLEN) fma2(acc[i], TAP2(t), x);
        }
    }
#pragma unroll
    for (int i = 0; i < 12; i++)
        d_mg[base + (size_t)(hb+i)*W_ + w0 + tx] = acc[i];
}

// ---------------------------------------------------------------------------
// K3: D-blur both fields (packed) + dot/sum reduction + last-block finalize.
__global__ __launch_bounds__(256) void blurD_reduce_kernel(float* __restrict__ out) {
    __shared__ u64 sh[DP][32];         // 30720 B
    __shared__ u64 sk[13];
    __shared__ float rn[256], rd[256];
    __shared__ bool isLast;
    const int tx = threadIdx.x, ty = threadIdx.y;
    const int tid = ty * 32 + tx;
    const int w0 = blockIdx.x * 32, h = blockIdx.y, b = blockIdx.z;
    size_t base = (size_t)b*VOL + (size_t)h*W_ + w0 + tx;

    make_taps(sk, tid);
    for (int dl = ty; dl < DP; dl += 8) {
        int gd = dl - RAD;
        bool ok = (unsigned)gd < (unsigned)D_;
        size_t idx = base + (size_t)(ok ? gd : 0) * (H_*W_);
        sh[dl][tx] = ok ? d_mg[idx] : 0ULL;
    }
    __syncthreads();

    u64 kp[13];
#pragma unroll
    for (int t = 0; t < 13; t++) kp[t] = sk[t];

    const int db = ty * 12;
    u64 acc[12] = {0,0,0,0,0,0,0,0,0,0,0,0};
#pragma unroll
    for (int j = 0; j < 12 + 2*RAD; j++) {
        u64 x = sh[db + j][tx];
#pragma unroll
        for (int i = 0; i < 12; i++) {
            int t = j - i;
            if (t >= 0 && t < KLEN) fma2(acc[i], TAP2(t), x);
        }
    }
    float num = 0.0f, den = 0.0f;
#pragma unroll
    for (int i = 0; i < 12; i++) {
        float2 v = unpack2(acc[i]);
        num += v.x * v.y;
        den += v.y;
    }

    rn[tid] = num; rd[tid] = den;
    __syncthreads();
    for (int s = 128; s > 0; s >>= 1) {
        if (tid < s) { rn[tid] += rn[tid + s]; rd[tid] += rd[tid + s]; }
        __syncthreads();
    }
    if (tid == 0) {
        int pb = blockIdx.y * gridDim.x + blockIdx.x;
        d_pnum[b*NPART + pb] = rn[0];
        d_pden[b*NPART + pb] = rd[0];
        __threadfence();
        unsigned prev = atomicAdd(&d_count, 1u);
        isLast = (prev == (unsigned)(K3_BLOCKS - 1));
    }
    __syncthreads();

    if (isLast) {
        __threadfence();
        for (int bb = 0; bb < B_; bb++) {
            float n = 0.0f, dsum = 0.0f;
            for (int i = tid; i < NPART; i += 256) {
                n    += d_pnum[bb*NPART + i];
                dsum += d_pden[bb*NPART + i];
            }
            rn[tid] = n; rd[tid] = dsum;
            __syncthreads();
            for (int s = 128; s > 0; s >>= 1) {
                if (tid < s) { rn[tid] += rn[tid + s]; rd[tid] += rd[tid + s]; }
                __syncthreads();
            }
            if (tid == 0) out[bb] = expf(-(rn[0] / (rd[0] + 1.0f)));
            __syncthreads();
        }
        if (tid == 0) d_count = 0;   // reset for next graph replay
    }
}

// ---------------------------------------------------------------------------
extern "C" void kernel_launch(void* const* d_in, const int* in_sizes, int n_in,
                              void* d_out, int out_size) {
    (void)in_sizes; (void)n_in; (void)out_size;
    const float* outs = (const float*)d_in[0];
    const float* guid = (const float*)d_in[1];
    float* out = (float*)d_out;

    {   // K1: pipelined sobel + W-blur -> d_mg
        dim3 grid(H_/HT, NSLAB, B_);
        dim3 blk(32, HT);
        sobel_blurW_kernel<<<grid, blk>>>(outs, guid);
    }
    {   // K2: H-blur in place
        dim3 grid(W_/16, D_, B_);
        dim3 blk(16, 16);
        blurH_kernel<<<grid, blk>>>();
    }
    {   // K3: D-blur + reduction + finalize
        dim3 grid(W_/32, H_, B_);
        dim3 blk(32, 8);
        blurD_reduce_kernel<<<grid, blk>>>(out);
    }
}